// round 5
// baseline (speedup 1.0000x reference)
#include <cuda_runtime.h>
#include <cuda_bf16.h>
#include <math_constants.h>

#define ROWS 8192
#define COLS 8192
#define NG   64
#define TPB  32                       // one warp per block; thread = row
#define CCHUNK 1024                   // columns per block
#define NCHUNK (COLS / CCHUNK)        // 8
#define NROWBLK (ROWS / TPB)          // 256
#define NOUT (ROWS * NG)              // 524288 per output tensor

// Partial min/max per (chunk, row, group): plain stores, no atomics. 33.5 MB.
__device__ float2   g_part[(size_t)NCHUNK * ROWS * NG];
// Arrival counters per row-block (zero-initialized at load; last block resets).
__device__ unsigned g_cnt[NROWBLK];

__global__ __launch_bounds__(TPB, 14) void obs_fused_kernel(
    const float* __restrict__ obs, const int* __restrict__ gidx,
    float* __restrict__ out)
{
    // Accumulators are THREAD-PRIVATE (slot g*32+t touched only by thread t):
    // no staging, no __syncthreads anywhere in the hot path.
    __shared__ float2 sacc[NG * TPB];   // 16 KB -> 14 blocks/SM

    const int t   = threadIdx.x;
    const int bx  = blockIdx.x;         // chunk id
    const int by  = blockIdx.y;         // row-block id
    const int c0  = bx * CCHUNK;
    const int row = by * TPB + t;

    #pragma unroll
    for (int g = 0; g < NG; g++)
        sacc[g * TPB + t] = make_float2(CUDART_INF_F, -CUDART_INF_F);

    const float4* rp = (const float4*)(obs + (size_t)row * COLS + c0);
    const int4*   gp = (const int4*)(gidx + c0);   // warp-uniform, L1-hot

    // 16 columns per iteration: 4x LDG.128 prefetched + SMEM RMW.
    float4 a0 = rp[0], a1 = rp[1], a2 = rp[2], a3 = rp[3];

    #pragma unroll 1
    for (int j = 0; j < CCHUNK / 16; j++) {
        float4 n0, n1, n2, n3;
        if (j + 1 < CCHUNK / 16) {
            const float4* np = rp + (j + 1) * 4;
            n0 = np[0]; n1 = np[1]; n2 = np[2]; n3 = np[3];
        }
        int4 gq0 = __ldg(&gp[j * 4 + 0]);
        int4 gq1 = __ldg(&gp[j * 4 + 1]);
        int4 gq2 = __ldg(&gp[j * 4 + 2]);
        int4 gq3 = __ldg(&gp[j * 4 + 3]);

        #define UPD(VAL, G) do {                         \
            float2 _a = sacc[(G) * TPB + t];             \
            _a.x = fminf(_a.x, (VAL));                   \
            _a.y = fmaxf(_a.y, (VAL));                   \
            sacc[(G) * TPB + t] = _a;                    \
        } while (0)

        UPD(a0.x, gq0.x); UPD(a0.y, gq0.y); UPD(a0.z, gq0.z); UPD(a0.w, gq0.w);
        UPD(a1.x, gq1.x); UPD(a1.y, gq1.y); UPD(a1.z, gq1.z); UPD(a1.w, gq1.w);
        UPD(a2.x, gq2.x); UPD(a2.y, gq2.y); UPD(a2.z, gq2.z); UPD(a2.w, gq2.w);
        UPD(a3.x, gq3.x); UPD(a3.y, gq3.y); UPD(a3.z, gq3.z); UPD(a3.w, gq3.w);
        #undef UPD

        a0 = n0; a1 = n1; a2 = n2; a3 = n3;
    }

    // ---- Flush: vectorized plain stores to unique partial slots ----
    {
        float4* pp = (float4*)&g_part[((size_t)bx * ROWS + row) * NG];
        #pragma unroll
        for (int g = 0; g < NG; g += 2) {
            float2 a = sacc[g * TPB + t];
            float2 b = sacc[(g + 1) * TPB + t];
            pp[g >> 1] = make_float4(a.x, a.y, b.x, b.y);
        }
    }

    // ---- Arrival protocol: last block of this row-set finalizes ----
    __threadfence();
    unsigned old = 0;
    if (t == 0) old = atomicAdd(&g_cnt[by], 1u);
    old = __shfl_sync(0xFFFFFFFFu, old, 0);
    if (old != NCHUNK - 1) return;

    __threadfence();            // acquire: all blocks' partials now visible
    if (t == 0) g_cnt[by] = 0;  // self-reset for next graph replay

    const float rcp15 = __uint_as_float(0x3D888889u);  // XLA's rounded 1/15
    const int rbase = by * TPB;

    // Lane t owns groups {2t, 2t+1}; loop rows. Coalesced 512B float4 loads.
    for (int r = 0; r < TPB; r++) {
        size_t base = ((size_t)rbase + r) * NG;
        const float4* q0 = (const float4*)&g_part[base];
        float4 a = q0[t];   // {min(2t), max(2t), min(2t+1), max(2t+1)} chunk 0
        #pragma unroll
        for (int c = 1; c < NCHUNK; c++) {
            const float4* qc = (const float4*)&g_part[(size_t)c * ROWS * NG + base];
            float4 b = qc[t];
            a.x = fminf(a.x, b.x); a.y = fmaxf(a.y, b.y);
            a.z = fminf(a.z, b.z); a.w = fmaxf(a.w, b.w);
        }
        float mn0 = fminf(a.x, 0.0f), mx0 = fmaxf(a.y, 0.0f);
        float mn1 = fminf(a.z, 0.0f), mx1 = fmaxf(a.w, 0.0f);
        float sc0 = fmaxf((mx0 - mn0) * rcp15, 1.1920929e-07f);
        float sc1 = fmaxf((mx1 - mn1) * rcp15, 1.1920929e-07f);
        float zp0 = rintf(-8.0f - __fdiv_rn(mn0, sc0));
        float zp1 = rintf(-8.0f - __fdiv_rn(mn1, sc1));
        zp0 = fminf(fmaxf(zp0, -8.0f), 7.0f);
        zp1 = fminf(fmaxf(zp1, -8.0f), 7.0f);
        int o = (rbase + r) * NG + 2 * t;
        ((float2*)(out + o))[0]        = make_float2(sc0, sc1);   // scale
        ((float2*)(out + NOUT + o))[0] = make_float2(zp0, zp1);   // zero_point
    }
}

extern "C" void kernel_launch(void* const* d_in, const int* in_sizes, int n_in,
                              void* d_out, int out_size) {
    const float* obs  = (const float*)d_in[0];
    const int*   gidx = (const int*)d_in[1];
    float* out = (float*)d_out;

    dim3 grid(NCHUNK, NROWBLK);   // 8 x 256 = 2048 blocks, one full wave
    obs_fused_kernel<<<grid, TPB>>>(obs, gidx, out);
}

// round 6
// speedup vs baseline: 1.2272x; 1.2272x over previous
#include <cuda_runtime.h>
#include <cuda_bf16.h>
#include <math_constants.h>

#define ROWS 8192
#define COLS 8192
#define NG   64
#define TPB  32                       // one warp per block; thread = row
#define CCHUNK 1024                   // columns per block
#define NIT   (CCHUNK / 16)           // 64 inner iterations
#define NCHUNK (COLS / CCHUNK)        // 8
#define NROWBLK (ROWS / TPB)          // 256
#define NOUT (ROWS * NG)              // 524288 per output tensor

// Partial min/max per (chunk, row, group): plain stores, no atomics. 33.5 MB.
__device__ float2   g_part[(size_t)NCHUNK * ROWS * NG];
// Arrival counters per row-block (zero-initialized at load; last block resets).
__device__ unsigned g_cnt[NROWBLK];

__global__ __launch_bounds__(TPB, 13) void obs_fused_kernel(
    const float* __restrict__ obs, const int* __restrict__ gidx,
    float* __restrict__ out)
{
    __shared__ float2 sacc[NG * TPB];        // 16 KB accumulators
    __shared__ __align__(16) unsigned sgb[CCHUNK / 4];  // 1 KB packed group ids

    const int t   = threadIdx.x;
    const int bx  = blockIdx.x;         // chunk id
    const int by  = blockIdx.y;         // row-block id
    const int c0  = bx * CCHUNK;
    const int row = by * TPB + t;

    // Stage group ids as bytes: each thread packs 32 ids (8 int4 -> 8 uint).
    {
        const int4* gv = (const int4*)(gidx + c0) + t * 8;
        unsigned p[8];
        #pragma unroll
        for (int i = 0; i < 8; i++) {
            int4 g = gv[i];
            p[i] = (unsigned)g.x | ((unsigned)g.y << 8) |
                   ((unsigned)g.z << 16) | ((unsigned)g.w << 24);
        }
        ((uint4*)sgb)[t * 2 + 0] = make_uint4(p[0], p[1], p[2], p[3]);
        ((uint4*)sgb)[t * 2 + 1] = make_uint4(p[4], p[5], p[6], p[7]);
    }
    #pragma unroll
    for (int g = 0; g < NG; g++)
        sacc[g * TPB + t] = make_float2(CUDART_INF_F, -CUDART_INF_F);
    __syncthreads();   // TPB==32: warp-level barrier, cheap

    const float4* rp = (const float4*)(obs + (size_t)row * COLS + c0);
    float2* acc = sacc + t;

    #define UPD(VAL, G) do {                      \
        float2 _a = acc[(G) * TPB];               \
        _a.x = fminf(_a.x, (VAL));                \
        _a.y = fmaxf(_a.y, (VAL));                \
        acc[(G) * TPB] = _a;                      \
    } while (0)

    // One LDS.128 broadcast feeds 16 UPDs.
    #define BODY(A0, A1, A2, A3, J) do {                                  \
        uint4 gw = ((const uint4*)sgb)[(J)];                              \
        UPD((A0).x, (gw.x      ) & 0xFF); UPD((A0).y, (gw.x >>  8) & 0xFF); \
        UPD((A0).z, (gw.x >> 16) & 0xFF); UPD((A0).w, (gw.x >> 24)       ); \
        UPD((A1).x, (gw.y      ) & 0xFF); UPD((A1).y, (gw.y >>  8) & 0xFF); \
        UPD((A1).z, (gw.y >> 16) & 0xFF); UPD((A1).w, (gw.y >> 24)       ); \
        UPD((A2).x, (gw.z      ) & 0xFF); UPD((A2).y, (gw.z >>  8) & 0xFF); \
        UPD((A2).z, (gw.z >> 16) & 0xFF); UPD((A2).w, (gw.z >> 24)       ); \
        UPD((A3).x, (gw.w      ) & 0xFF); UPD((A3).y, (gw.w >>  8) & 0xFF); \
        UPD((A3).z, (gw.w >> 16) & 0xFF); UPD((A3).w, (gw.w >> 24)       ); \
    } while (0)

    // Prefetch distance 2: 8 LDG.128 in flight (MLP=8).
    float4 c0v = rp[0], c1 = rp[1], c2 = rp[2], c3 = rp[3];
    float4 d0 = rp[4], d1 = rp[5], d2 = rp[6], d3 = rp[7];

    #pragma unroll 1
    for (int j = 0; j < NIT; j += 2) {
        float4 p0, p1, p2, p3;
        if (j + 2 < NIT) {
            const float4* np = rp + (j + 2) * 4;
            p0 = np[0]; p1 = np[1]; p2 = np[2]; p3 = np[3];
        }
        BODY(c0v, c1, c2, c3, j);
        c0v = p0; c1 = p1; c2 = p2; c3 = p3;

        float4 q0, q1, q2, q3;
        if (j + 3 < NIT) {
            const float4* nq = rp + (j + 3) * 4;
            q0 = nq[0]; q1 = nq[1]; q2 = nq[2]; q3 = nq[3];
        }
        BODY(d0, d1, d2, d3, j + 1);
        d0 = q0; d1 = q1; d2 = q2; d3 = q3;
    }
    #undef BODY
    #undef UPD

    // ---- Flush: vectorized plain stores to unique partial slots ----
    {
        float4* pp = (float4*)&g_part[((size_t)bx * ROWS + row) * NG];
        #pragma unroll
        for (int g = 0; g < NG; g += 2) {
            float2 a = sacc[g * TPB + t];
            float2 b = sacc[(g + 1) * TPB + t];
            pp[g >> 1] = make_float4(a.x, a.y, b.x, b.y);
        }
    }

    // ---- Arrival protocol: last block of this row-set finalizes ----
    __threadfence();
    unsigned old = 0;
    if (t == 0) old = atomicAdd(&g_cnt[by], 1u);
    old = __shfl_sync(0xFFFFFFFFu, old, 0);
    if (old != NCHUNK - 1) return;

    __threadfence();            // acquire: all blocks' partials now visible
    if (t == 0) g_cnt[by] = 0;  // self-reset for next graph replay

    const float rcp15 = __uint_as_float(0x3D888889u);  // XLA's rounded 1/15
    const int rbase = by * TPB;

    // Lane t owns groups {2t, 2t+1}; loop rows. Coalesced 512B float4 loads.
    for (int r = 0; r < TPB; r++) {
        size_t base = ((size_t)rbase + r) * NG;
        const float4* q0 = (const float4*)&g_part[base];
        float4 a = q0[t];   // {min(2t), max(2t), min(2t+1), max(2t+1)} chunk 0
        #pragma unroll
        for (int c = 1; c < NCHUNK; c++) {
            const float4* qc = (const float4*)&g_part[(size_t)c * ROWS * NG + base];
            float4 b = qc[t];
            a.x = fminf(a.x, b.x); a.y = fmaxf(a.y, b.y);
            a.z = fminf(a.z, b.z); a.w = fmaxf(a.w, b.w);
        }
        float mn0 = fminf(a.x, 0.0f), mx0 = fmaxf(a.y, 0.0f);
        float mn1 = fminf(a.z, 0.0f), mx1 = fmaxf(a.w, 0.0f);
        float sc0 = fmaxf((mx0 - mn0) * rcp15, 1.1920929e-07f);
        float sc1 = fmaxf((mx1 - mn1) * rcp15, 1.1920929e-07f);
        float zp0 = rintf(-8.0f - __fdiv_rn(mn0, sc0));
        float zp1 = rintf(-8.0f - __fdiv_rn(mn1, sc1));
        zp0 = fminf(fmaxf(zp0, -8.0f), 7.0f);
        zp1 = fminf(fmaxf(zp1, -8.0f), 7.0f);
        int o = (rbase + r) * NG + 2 * t;
        ((float2*)(out + o))[0]        = make_float2(sc0, sc1);   // scale
        ((float2*)(out + NOUT + o))[0] = make_float2(zp0, zp1);   // zero_point
    }
}

extern "C" void kernel_launch(void* const* d_in, const int* in_sizes, int n_in,
                              void* d_out, int out_size) {
    const float* obs  = (const float*)d_in[0];
    const int*   gidx = (const int*)d_in[1];
    float* out = (float*)d_out;

    dim3 grid(NCHUNK, NROWBLK);   // 8 x 256 = 2048 blocks
    obs_fused_kernel<<<grid, TPB>>>(obs, gidx, out);
}

// round 7
// speedup vs baseline: 1.2784x; 1.0417x over previous
#include <cuda_runtime.h>
#include <cuda_bf16.h>
#include <math_constants.h>

#define ROWS 8192
#define COLS 8192
#define NG   64
#define TPB  32                       // one warp per block; thread = row
#define CCHUNK 1024                   // columns per block
#define NB    (CCHUNK / 32)           // 32 batches of 32 columns
#define NCHUNK (COLS / CCHUNK)        // 8
#define NROWBLK (ROWS / TPB)          // 256
#define NOUT (ROWS * NG)              // 524288 per output tensor

// Partial min/max per (chunk, row, group): plain stores, no atomics. 33.5 MB.
__device__ float2   g_part[(size_t)NCHUNK * ROWS * NG];
// Arrival counters per row-block (zero-initialized at load; last block resets).
__device__ unsigned g_cnt[NROWBLK];

__global__ __launch_bounds__(TPB, 13) void obs_fused_kernel(
    const float* __restrict__ obs, const int* __restrict__ gidx,
    float* __restrict__ out)
{
    __shared__ float2 sacc[NG * TPB];                   // 16 KB accumulators
    __shared__ __align__(16) unsigned sgb[CCHUNK / 4];  // 1 KB packed group ids

    const int t   = threadIdx.x;
    const int bx  = blockIdx.x;         // chunk id
    const int by  = blockIdx.y;         // row-block id
    const int c0  = bx * CCHUNK;
    const int row = by * TPB + t;

    // Stage group ids as bytes: each thread packs 32 ids (8 int4 -> 8 uint).
    {
        const int4* gv = (const int4*)(gidx + c0) + t * 8;
        unsigned p[8];
        #pragma unroll
        for (int i = 0; i < 8; i++) {
            int4 g = gv[i];
            p[i] = (unsigned)g.x | ((unsigned)g.y << 8) |
                   ((unsigned)g.z << 16) | ((unsigned)g.w << 24);
        }
        ((uint4*)sgb)[t * 2 + 0] = make_uint4(p[0], p[1], p[2], p[3]);
        ((uint4*)sgb)[t * 2 + 1] = make_uint4(p[4], p[5], p[6], p[7]);
    }
    #pragma unroll
    for (int g = 0; g < NG; g++)
        sacc[g * TPB + t] = make_float2(CUDART_INF_F, -CUDART_INF_F);
    __syncthreads();   // TPB==32: warp-level barrier, cheap

    const float4* rp = (const float4*)(obs + (size_t)row * COLS + c0);
    const uint4*  sg4 = (const uint4*)sgb;
    char* accbase = (char*)sacc + t * 8;   // lane-private column of sacc

    // UPD: OFF is the byte offset G*256, produced directly by PRMT.
    #define UPD(VAL, OFF) do {                              \
        float2* _p = (float2*)(accbase + (OFF));            \
        float2 _a = *_p;                                    \
        _a.x = fminf(_a.x, (VAL));                          \
        _a.y = fmaxf(_a.y, (VAL));                          \
        *_p = _a;                                           \
    } while (0)

    // One uint of packed ids serves one float4 (4 columns). byte k -> byte1
    // of result == id<<8 == G*256 (float2 stride 8B * 32 lanes = 256B/group).
    #define UPD4(F4, GW) do {                               \
        UPD((F4).x, __byte_perm((GW), 0, 0x4404));          \
        UPD((F4).y, __byte_perm((GW), 0, 0x4414));          \
        UPD((F4).z, __byte_perm((GW), 0, 0x4424));          \
        UPD((F4).w, __byte_perm((GW), 0, 0x4434));          \
    } while (0)

    // 32-column batches: 8 LDG.128 issued back-to-back (deep MLP), then
    // 32 SMEM RMWs; next batch prefetched during the RMWs.
    float4 A[8];
    #pragma unroll
    for (int i = 0; i < 8; i++) A[i] = rp[i];

    #pragma unroll 1
    for (int j = 0; j < NB; j++) {
        float4 P[8];
        if (j + 1 < NB) {
            const float4* np = rp + (j + 1) * 8;
            #pragma unroll
            for (int i = 0; i < 8; i++) P[i] = np[i];
        }
        uint4 wa = sg4[j * 2 + 0];
        uint4 wb = sg4[j * 2 + 1];
        UPD4(A[0], wa.x); UPD4(A[1], wa.y);
        UPD4(A[2], wa.z); UPD4(A[3], wa.w);
        UPD4(A[4], wb.x); UPD4(A[5], wb.y);
        UPD4(A[6], wb.z); UPD4(A[7], wb.w);
        #pragma unroll
        for (int i = 0; i < 8; i++) A[i] = P[i];
    }
    #undef UPD4
    #undef UPD

    // ---- Flush: vectorized plain stores to unique partial slots ----
    {
        float4* pp = (float4*)&g_part[((size_t)bx * ROWS + row) * NG];
        #pragma unroll
        for (int g = 0; g < NG; g += 2) {
            float2 a = sacc[g * TPB + t];
            float2 b = sacc[(g + 1) * TPB + t];
            pp[g >> 1] = make_float4(a.x, a.y, b.x, b.y);
        }
    }

    // ---- Arrival protocol: last block of this row-set finalizes ----
    __threadfence();
    unsigned old = 0;
    if (t == 0) old = atomicAdd(&g_cnt[by], 1u);
    old = __shfl_sync(0xFFFFFFFFu, old, 0);
    if (old != NCHUNK - 1) return;

    __threadfence();            // acquire: all blocks' partials now visible
    if (t == 0) g_cnt[by] = 0;  // self-reset for next graph replay

    const float rcp15 = __uint_as_float(0x3D888889u);  // XLA's rounded 1/15
    const int rbase = by * TPB;

    // Lane t owns groups {2t, 2t+1}; loop rows. Coalesced 512B float4 loads.
    for (int r = 0; r < TPB; r++) {
        size_t base = ((size_t)rbase + r) * NG;
        const float4* q0 = (const float4*)&g_part[base];
        float4 a = q0[t];   // {min(2t), max(2t), min(2t+1), max(2t+1)} chunk 0
        #pragma unroll
        for (int c = 1; c < NCHUNK; c++) {
            const float4* qc = (const float4*)&g_part[(size_t)c * ROWS * NG + base];
            float4 b = qc[t];
            a.x = fminf(a.x, b.x); a.y = fmaxf(a.y, b.y);
            a.z = fminf(a.z, b.z); a.w = fmaxf(a.w, b.w);
        }
        float mn0 = fminf(a.x, 0.0f), mx0 = fmaxf(a.y, 0.0f);
        float mn1 = fminf(a.z, 0.0f), mx1 = fmaxf(a.w, 0.0f);
        float sc0 = fmaxf((mx0 - mn0) * rcp15, 1.1920929e-07f);
        float sc1 = fmaxf((mx1 - mn1) * rcp15, 1.1920929e-07f);
        float zp0 = rintf(-8.0f - __fdiv_rn(mn0, sc0));
        float zp1 = rintf(-8.0f - __fdiv_rn(mn1, sc1));
        zp0 = fminf(fmaxf(zp0, -8.0f), 7.0f);
        zp1 = fminf(fmaxf(zp1, -8.0f), 7.0f);
        int o = (rbase + r) * NG + 2 * t;
        ((float2*)(out + o))[0]        = make_float2(sc0, sc1);   // scale
        ((float2*)(out + NOUT + o))[0] = make_float2(zp0, zp1);   // zero_point
    }
}

extern "C" void kernel_launch(void* const* d_in, const int* in_sizes, int n_in,
                              void* d_out, int out_size) {
    const float* obs  = (const float*)d_in[0];
    const int*   gidx = (const int*)d_in[1];
    float* out = (float*)d_out;

    dim3 grid(NCHUNK, NROWBLK);   // 8 x 256 = 2048 blocks
    obs_fused_kernel<<<grid, TPB>>>(obs, gidx, out);
}